// round 4
// baseline (speedup 1.0000x reference)
#include <cuda_runtime.h>

// out[i,m,l] = w1[i,0]*t4[i,(m-1)%56,l] + w1[i,1]*t4[i,(m-2)%56,l]
// t4[i,n,l]  = sum_{j,k} x[j,n,l+k-1] * w2[i,j,k]   (zero-padded 3-tap)
//
// One block per (channel-half ihalf, output row m). f32x2 lanes carry the two
// needed t4 rows (na=m-1, nb=m-2): x is stored row-interleaved in smem and
// weights pre-duplicated, so every FFMA2 operand comes straight from one
// LDS.64 with zero pack MOVs.
// 512 threads = jq(4 j-quarters) x ip(16 channel-pairs) x lg(8 col groups).

using ull = unsigned long long;

__device__ __forceinline__ ull pack2(float lo, float hi) {
    ull r; asm("mov.b64 %0, {%1, %2};" : "=l"(r) : "f"(lo), "f"(hi)); return r;
}
__device__ __forceinline__ ull fma2(ull a, ull b, ull c) {
    ull d; asm("fma.rn.f32x2 %0, %1, %2, %3;" : "=l"(d) : "l"(a), "l"(b), "l"(c)); return d;
}
__device__ __forceinline__ ull add2(ull a, ull b) {
    ull d; asm("add.rn.f32x2 %0, %1, %2;" : "=l"(d) : "l"(a), "l"(b)); return d;
}
__device__ __forceinline__ void unpack2(ull p, float& lo, float& hi) {
    asm("mov.b64 {%0, %1}, %2;" : "=f"(lo), "=f"(hi) : "l"(p));
}

// smem arena (ull units):
//   xs2 : 64*58  row-interleaved x pairs                [0 .. 3712)
//   w2d : 32*192 duplicated weights {w,w}               [3712 .. 9856)
//   rbuf: overlays arena after main loop: 512*15 = 7680 ull
static constexpr int XS2_OFF = 0;
static constexpr int W2D_OFF = 64 * 58;                    // 3712
static constexpr int ARENA_ULL = W2D_OFF + 32 * 192;       // 9856
static constexpr int ARENA_BYTES = ARENA_ULL * 8;          // 78848

__global__ __launch_bounds__(512, 1) void fused_kernel(
    const float* __restrict__ x,
    const float* __restrict__ w1,
    const float* __restrict__ w2,
    float* __restrict__ out) {

    extern __shared__ ull arena[];
    ull* xs2 = arena + XS2_OFF;
    ull* w2d = arena + W2D_OFF;

    const int m     = blockIdx.y;
    const int ihalf = blockIdx.x;
    const int ibase = ihalf * 32;
    const int na    = (m + 55) % 56;
    const int nb    = (m + 54) % 56;
    const int tid   = threadIdx.x;

    // Halo zeros at padded cols 0 and 57.
    if (tid < 128) {
        int j = tid >> 1;
        xs2[j * 58 + ((tid & 1) ? 57 : 0)] = 0ull;
    }

    // Load both x rows, interleaved into pairs: xs2[j*58+1+l] = {x[na], x[nb]}.
    for (int idx = tid; idx < 64 * 14; idx += 512) {
        int j  = idx / 14;
        int c4 = idx % 14;
        float4 va = *reinterpret_cast<const float4*>(&x[(j * 56 + na) * 56 + c4 * 4]);
        float4 vb = *reinterpret_cast<const float4*>(&x[(j * 56 + nb) * 56 + c4 * 4]);
        ull* d = &xs2[j * 58 + 1 + c4 * 4];
        d[0] = pack2(va.x, vb.x);
        d[1] = pack2(va.y, vb.y);
        d[2] = pack2(va.z, vb.z);
        d[3] = pack2(va.w, vb.w);
    }

    // Duplicate-pack this half's weights: w2d[il*192+jk] = {w,w}.
    for (int idx = tid; idx < 32 * 192; idx += 512) {
        int il = idx / 192;
        int jk = idx % 192;
        float w = w2[(ibase + il) * 192 + jk];
        w2d[il * 192 + jk] = pack2(w, w);
    }
    __syncthreads();

    const int jq = tid >> 7;        // 0..3 : j-quarter
    const int t  = tid & 127;
    const int ip = t >> 3;          // 0..15 : channel pair
    const int lg = t & 7;           // 0..7  : column group
    const int l0 = lg * 7;
    const int j0 = jq * 16;
    const int il0 = 2 * ip;

    ull acc[2][7];
#pragma unroll
    for (int c = 0; c < 2; ++c)
#pragma unroll
        for (int q = 0; q < 7; ++q) acc[c][q] = 0ull;

#pragma unroll 4
    for (int jj = 0; jj < 16; ++jj) {
        const int j = j0 + jj;
        const ull* xp = &xs2[j * 58 + l0];
        ull pa[9];
#pragma unroll
        for (int q = 0; q < 9; ++q) pa[q] = xp[q];   // LDS.64, pair-ready

#pragma unroll
        for (int c = 0; c < 2; ++c) {
            const ull* wp = &w2d[(il0 + c) * 192 + 3 * j];
            const ull wk0 = wp[0];
            const ull wk1 = wp[1];
            const ull wk2 = wp[2];
#pragma unroll
            for (int q = 0; q < 7; ++q)
                acc[c][q] = fma2(pa[q], wk0,
                            fma2(pa[q + 1], wk1,
                            fma2(pa[q + 2], wk2, acc[c][q])));
        }
    }

    // 4-way jq reduction through smem, slot-parallel epilogue.
    __syncthreads();                       // xs2/w2d reads done before overlay
    ull* rbuf = arena;                     // 512*15 ull = 61440 B < arena
    {
        ull* dst = &rbuf[(jq * 128 + t) * 15];
#pragma unroll
        for (int c = 0; c < 2; ++c)
#pragma unroll
            for (int q = 0; q < 7; ++q) dst[c * 7 + q] = acc[c][q];
    }
    __syncthreads();

    // Each jq quarter finalizes a disjoint slot range of the 14 outputs.
    const int s0 = (jq * 14) / 4;
    const int s1 = ((jq + 1) * 14) / 4;
    for (int s = s0; s < s1; ++s) {
        ull v = add2(add2(rbuf[(0 * 128 + t) * 15 + s], rbuf[(1 * 128 + t) * 15 + s]),
                     add2(rbuf[(2 * 128 + t) * 15 + s], rbuf[(3 * 128 + t) * 15 + s]));
        int c = s / 7;
        int q = s % 7;
        int i = ibase + il0 + c;
        float a, b;
        unpack2(v, a, b);
        out[(i * 56 + m) * 56 + l0 + q] = fmaf(w1[2 * i], a, w1[2 * i + 1] * b);
    }
}

extern "C" void kernel_launch(void* const* d_in, const int* in_sizes, int n_in,
                              void* d_out, int out_size) {
    const float* x  = (const float*)d_in[0];   // (1,64,56,56)
    const float* w1 = (const float*)d_in[1];   // (64,2)
    const float* w2 = (const float*)d_in[2];   // (64,64,3)
    float* out = (float*)d_out;                // (1,64,56,56)

    static bool attr_set = false;
    if (!attr_set) {
        cudaFuncSetAttribute(fused_kernel,
                             cudaFuncAttributeMaxDynamicSharedMemorySize,
                             ARENA_BYTES);
        attr_set = true;
    }

    dim3 grid(2, 56);
    fused_kernel<<<grid, 512, ARENA_BYTES>>>(x, w1, w2, out);
}